// round 3
// baseline (speedup 1.0000x reference)
#include <cuda_runtime.h>
#include <cuda_bf16.h>

#define N_NODES 100000
#define N_EDGES 1600000
#define F_IN    165
#define F_HID   128
#define SCAN_CHUNK 1024
#define SCAN_NB ((N_NODES + SCAN_CHUNK - 1) / SCAN_CHUNK)   // 98

// ---- device scratch (allocation-free rule) ----
__device__ __align__(16) float g_h[N_NODES * F_HID];   // x @ W1
__device__ float g_dinv[N_NODES];
__device__ int   g_deg[N_NODES];
__device__ int   g_cursor[N_NODES];
__device__ int   g_rowstart[N_NODES + 1];
__device__ int   g_bsum[SCAN_NB];
__device__ int   g_src32[N_EDGES];
__device__ int   g_csr_src[N_EDGES];
__device__ float g_z[N_NODES];     // relu(agg+b1) . W4
__device__ float g_zd[N_NODES];    // z * dinv
__device__ int   g_is64;

// ---------------------------------------------------------------------------
// dtype detect: int64 node ids < 100000 -> every odd 32-bit word is 0
// ---------------------------------------------------------------------------
__global__ void k_detect(const int* __restrict__ ei32) {
    if (threadIdx.x == 0 && blockIdx.x == 0) {
        int z = 0;
        for (int i = 0; i < 16; i++) z |= ei32[2 * i + 1];
        g_is64 = (z == 0) ? 1 : 0;
    }
}

__device__ __forceinline__ int clampN(int v) {
    return min(max(v, 0), N_NODES - 1);
}

__global__ void k_init() {
    int i = blockIdx.x * blockDim.x + threadIdx.x;
    if (i < N_NODES) { g_deg[i] = 0; g_cursor[i] = 0; }
}

// degree count + dtype-aware conversion to int32 (src saved; dst consumed here)
__global__ void k_deg(const void* __restrict__ eiv) {
    const int is64 = g_is64;
    const long long* e64 = (const long long*)eiv;
    const int*       e32 = (const int*)eiv;
    int stride = gridDim.x * blockDim.x;
    for (int e = blockIdx.x * blockDim.x + threadIdx.x; e < N_EDGES; e += stride) {
        int s, d;
        if (is64) { s = (int)e64[e]; d = (int)e64[N_EDGES + e]; }
        else      { s = e32[e];      d = e32[N_EDGES + e]; }
        s = clampN(s); d = clampN(d);
        g_src32[e] = (s << 0);
        // temporally pack dst in high bits? no — store via cursor later; keep dst implicit
        atomicAdd(&g_deg[d], 1);
    }
}

__global__ void k_dinv() {
    int i = blockIdx.x * blockDim.x + threadIdx.x;
    if (i < N_NODES)
        g_dinv[i] = rsqrtf((float)(g_deg[i] + 1));   // +1: self loop
}

// ---- exclusive scan of deg -> rowstart ----
__global__ __launch_bounds__(SCAN_CHUNK) void k_scan1() {
    __shared__ int sm[SCAN_CHUNK];
    int tid = threadIdx.x;
    int i = blockIdx.x * SCAN_CHUNK + tid;
    int v = (i < N_NODES) ? g_deg[i] : 0;
    sm[tid] = v;
    __syncthreads();
    for (int off = 1; off < SCAN_CHUNK; off <<= 1) {
        int t = (tid >= off) ? sm[tid - off] : 0;
        __syncthreads();
        sm[tid] += t;
        __syncthreads();
    }
    if (i < N_NODES) g_rowstart[i] = sm[tid] - v;     // exclusive
    if (tid == SCAN_CHUNK - 1) g_bsum[blockIdx.x] = sm[tid];
}

__global__ void k_scan2() {
    if (threadIdx.x == 0 && blockIdx.x == 0) {
        int run = 0;
        for (int b = 0; b < SCAN_NB; b++) {
            int t = g_bsum[b];
            g_bsum[b] = run;
            run += t;
        }
    }
}

__global__ void k_scan3() {
    int i = blockIdx.x * blockDim.x + threadIdx.x;
    if (i < N_NODES) g_rowstart[i] += g_bsum[i / SCAN_CHUNK];
    if (i == 0) g_rowstart[N_NODES] = N_EDGES;
}

// CSR fill (int atomics on cursors only)
__global__ void k_fill(const void* __restrict__ eiv) {
    const int is64 = g_is64;
    const long long* e64 = (const long long*)eiv;
    const int*       e32 = (const int*)eiv;
    int stride = gridDim.x * blockDim.x;
    for (int e = blockIdx.x * blockDim.x + threadIdx.x; e < N_EDGES; e += stride) {
        int d = is64 ? (int)e64[N_EDGES + e] : e32[N_EDGES + e];
        d = clampN(d);
        int pos = g_rowstart[d] + atomicAdd(&g_cursor[d], 1);
        g_csr_src[pos] = g_src32[e];
    }
}

// ---------------------------------------------------------------------------
// GEMM: g_h = x[N,165] @ W1[165,128]; tile 64x128, K chunk 15, 256 thr
// ---------------------------------------------------------------------------
#define BM 64
#define BK 15

__global__ __launch_bounds__(256) void k_gemm1(const float* __restrict__ x,
                                               const float* __restrict__ W1) {
    __shared__ float xs[BM][BK + 2];
    __shared__ float ws[BK][F_HID];

    int t    = threadIdx.x;
    int row0 = blockIdx.x * BM;
    int trg  = t >> 4;
    int tcg  = t & 15;

    float acc[4][8];
#pragma unroll
    for (int i = 0; i < 4; i++)
#pragma unroll
        for (int j = 0; j < 8; j++) acc[i][j] = 0.f;

    for (int c = 0; c < 11; c++) {
        int k0 = c * BK;
        for (int idx = t; idx < BM * BK; idx += 256) {
            int r  = idx / BK;
            int kk = idx % BK;
            int row = row0 + r;
            xs[r][kk] = (row < N_NODES) ? x[row * F_IN + k0 + kk] : 0.f;
        }
        for (int idx = t; idx < BK * F_HID; idx += 256) {
            int kk = idx >> 7;
            int cc = idx & 127;
            ws[kk][cc] = W1[(k0 + kk) * F_HID + cc];
        }
        __syncthreads();

#pragma unroll
        for (int kk = 0; kk < BK; kk++) {
            float a[4];
#pragma unroll
            for (int i = 0; i < 4; i++) a[i] = xs[trg * 4 + i][kk];
            float4 b0 = *reinterpret_cast<const float4*>(&ws[kk][tcg * 8]);
            float4 b1 = *reinterpret_cast<const float4*>(&ws[kk][tcg * 8 + 4]);
#pragma unroll
            for (int i = 0; i < 4; i++) {
                acc[i][0] += a[i] * b0.x;  acc[i][1] += a[i] * b0.y;
                acc[i][2] += a[i] * b0.z;  acc[i][3] += a[i] * b0.w;
                acc[i][4] += a[i] * b1.x;  acc[i][5] += a[i] * b1.y;
                acc[i][6] += a[i] * b1.z;  acc[i][7] += a[i] * b1.w;
            }
        }
        __syncthreads();
    }

#pragma unroll
    for (int i = 0; i < 4; i++) {
        int row = row0 + trg * 4 + i;
        if (row < N_NODES) {
            float4 o0 = make_float4(acc[i][0], acc[i][1], acc[i][2], acc[i][3]);
            float4 o1 = make_float4(acc[i][4], acc[i][5], acc[i][6], acc[i][7]);
            *reinterpret_cast<float4*>(&g_h[row * F_HID + tcg * 8])     = o0;
            *reinterpret_cast<float4*>(&g_h[row * F_HID + tcg * 8 + 4]) = o1;
        }
    }
}

// ---------------------------------------------------------------------------
// Fused layer-1 aggregate + bias + ReLU + dot(W4): warp per dst node.
// ---------------------------------------------------------------------------
__global__ __launch_bounds__(256) void k_agg1(const float* __restrict__ b1,
                                              const float* __restrict__ W4) {
    int node = (blockIdx.x * blockDim.x + threadIdx.x) >> 5;
    int lane = threadIdx.x & 31;
    if (node >= N_NODES) return;

    int e0 = g_rowstart[node];
    int e1 = g_rowstart[node + 1];

    float4 acc = make_float4(0.f, 0.f, 0.f, 0.f);
    for (int base = e0; base < e1; base += 32) {
        int n = min(32, e1 - base);
        int s = 0; float dv = 0.f;
        if (base + lane < e1) {
            s  = g_csr_src[base + lane];
            dv = g_dinv[s];
        }
#pragma unroll 4
        for (int j = 0; j < n; j++) {
            int   sj = __shfl_sync(0xFFFFFFFFu, s,  j);
            float wj = __shfl_sync(0xFFFFFFFFu, dv, j);
            float4 hv = *reinterpret_cast<const float4*>(&g_h[sj * F_HID + lane * 4]);
            acc.x = fmaf(wj, hv.x, acc.x);
            acc.y = fmaf(wj, hv.y, acc.y);
            acc.z = fmaf(wj, hv.z, acc.z);
            acc.w = fmaf(wj, hv.w, acc.w);
        }
    }

    float dd = g_dinv[node];
    float self = dd * dd;
    float4 hv = *reinterpret_cast<const float4*>(&g_h[node * F_HID + lane * 4]);
    float4 bb = reinterpret_cast<const float4*>(b1)[lane];
    float4 ww = reinterpret_cast<const float4*>(W4)[lane];

    float r0 = fmaxf(fmaf(dd, acc.x, fmaf(self, hv.x, bb.x)), 0.f);
    float r1 = fmaxf(fmaf(dd, acc.y, fmaf(self, hv.y, bb.y)), 0.f);
    float r2 = fmaxf(fmaf(dd, acc.z, fmaf(self, hv.z, bb.z)), 0.f);
    float r3 = fmaxf(fmaf(dd, acc.w, fmaf(self, hv.w, bb.w)), 0.f);

    float dot = r0 * ww.x + r1 * ww.y + r2 * ww.z + r3 * ww.w;
#pragma unroll
    for (int o = 16; o > 0; o >>= 1)
        dot += __shfl_down_sync(0xFFFFFFFFu, dot, o);
    if (lane == 0) {
        g_z[node]  = dot;
        g_zd[node] = dot * dd;
    }
}

// ---------------------------------------------------------------------------
// Fused layer-2 gather + sigmoid: thread per node.
// ---------------------------------------------------------------------------
__global__ void k_out2(float* __restrict__ out, const float* __restrict__ b4) {
    int i = blockIdx.x * blockDim.x + threadIdx.x;
    if (i >= N_NODES) return;
    int e0 = g_rowstart[i];
    int e1 = g_rowstart[i + 1];
    float a = 0.f;
    for (int e = e0; e < e1; e++)
        a += g_zd[g_csr_src[e]];
    float dd = g_dinv[i];
    float v = fmaf(dd, a, dd * dd * g_z[i]) + b4[0];
    out[i] = 1.f / (1.f + expf(-v));
}

// ---------------------------------------------------------------------------
extern "C" void kernel_launch(void* const* d_in, const int* in_sizes, int n_in,
                              void* d_out, int out_size) {
    const float* x  = (const float*)d_in[0];
    const void*  ei = d_in[1];
    const float* W1 = (const float*)d_in[2];
    const float* b1 = (const float*)d_in[3];
    const float* W4 = (const float*)d_in[4];
    const float* b4 = (const float*)d_in[5];
    float* out = (float*)d_out;

    k_detect<<<1, 32>>>((const int*)ei);
    k_init<<<(N_NODES + 255) / 256, 256>>>();
    k_deg<<<2048, 256>>>(ei);
    k_dinv<<<(N_NODES + 255) / 256, 256>>>();
    k_scan1<<<SCAN_NB, SCAN_CHUNK>>>();
    k_scan2<<<1, 32>>>();
    k_scan3<<<(N_NODES + 255) / 256, 256>>>();
    k_fill<<<2048, 256>>>(ei);
    k_gemm1<<<(N_NODES + BM - 1) / BM, 256>>>(x, W1);
    k_agg1<<<(N_NODES * 32 + 255) / 256, 256>>>(b1, W4);
    k_out2<<<(N_NODES + 255) / 256, 256>>>(out, b4);
}